// round 16
// baseline (speedup 1.0000x reference)
#include <cuda_runtime.h>
#include <math.h>

#define BB 256
#define TT 512
#define II 128
#define HH 256
#define H2 512
#define H3 768
#define SMS 148
#define GRID 148
#define NTHR 128
#define GSTRIDE (GRID * NTHR)

typedef unsigned long long ull;

// BK=16 staging geometry for the 32x128 tile
#define A_PITCH 18                 // ull per k-row (16 row-pairs + 2 pad)
#define W_PITCH 132                // f32 per k-row (128 cols + 4 pad)
#define ABUF (16 * A_PITCH)        // 288 ull
#define WBUF (16 * W_PITCH)        // 2112 f32

enum { EPI_RAW = 0, EPI_TANH = 2 };

// ---------------- persistent device scratch (no allocations) ----------------
__device__ float g_W1t[H2 * H2];     // transposed: Wt[k][n] = W[n][k]
__device__ float g_W2t[H2 * H2];
__device__ float g_W3t[H2 * H2];
__device__ float g_WihT[HH * H3];
__device__ float g_WhhT[HH * H3];
__device__ float g_WcinT[II * HH];

__device__ float g_com[BB][H2];      // [c | c_in_t]
__device__ float g_a1p[8][BB][H2];   // MLP K-split-8 partials
__device__ float g_a2p[8][BB][H2];
__device__ float g_a3p[8][BB][H2];
__device__ float g_gip[4][BB][H3];   // gate K-split-4 partials (no bias)
__device__ float g_ghp[4][BB][H3];
__device__ float g_c[BB][HH];
__device__ float g_h[BB][HH];
__device__ float g_n[BB];

// ---------------- hierarchical barrier (monotonic, replay-safe) ----------------
__device__ unsigned g_cntG[32 * 32];
__device__ volatile unsigned g_genG;
__device__ unsigned g_epochG;

__device__ __forceinline__ void barrier_G(unsigned k)
{
    __syncthreads();
    if (threadIdx.x == 0) {
        __threadfence();
        atomicAdd(&g_cntG[(blockIdx.x & 31) << 5], 1u);
        if (blockIdx.x == 0) {
            unsigned long long need = (unsigned long long)k * GRID;
            for (;;) {
                unsigned long long s = 0;
#pragma unroll
                for (int i = 0; i < 32; i++)
                    s += ((volatile unsigned*)g_cntG)[i << 5];
                if (s >= need) break;
                __nanosleep(64);
            }
            __threadfence();
            g_genG = k;
        } else {
            while (g_genG < k) __nanosleep(96);
        }
        __threadfence();
    }
    __syncthreads();
}

__device__ __forceinline__ float sigf(float x) { return 1.f / (1.f + expf(-x)); }

__device__ __forceinline__ ull pack2(float x, float y) {
    ull r; asm("mov.b64 %0,{%1,%2};" : "=l"(r) : "f"(x), "f"(y)); return r;
}
__device__ __forceinline__ void unpack2(ull v, float& x, float& y) {
    asm("mov.b64 {%0,%1},%2;" : "=f"(x), "=f"(y) : "l"(v));
}
__device__ __forceinline__ void fma2(ull& d, ull a, ull b) {
    asm("fma.rn.f32x2 %0, %1, %2, %0;" : "+l"(d) : "l"(a), "l"(b));
}

// -------------------------------------------------------------------------
// 32x128 output tile, K = nkt*16, 128 threads, per-thread 4x8.
// (R15 gemm4x8 arithmetic verbatim; NSRC generalized: A = relu(sum of NSRC
// partials + kb) folded into the prefetch. 1 CTA/SM -> crossbar has slack.)
// -------------------------------------------------------------------------
template<int EPI, int NSRC>
__device__ __noinline__ void gemm4x8(
    const float* __restrict__ A0, size_t srcStride, const float* __restrict__ kb,
    int lda, int koff,
    const float* __restrict__ Wt, int ldw,
    const float* __restrict__ bias,
    float* __restrict__ C, int ldc,
    int rowBase, int colBase, int nkt,
    ull* __restrict__ As, float* __restrict__ Ws)
{
    const int tid = threadIdx.x;
    const int tx  = tid & 15;       // cols 4tx..4tx+3 and 64+4tx..64+4tx+3
    const int ty  = tid >> 4;       // rows 4ty..4ty+3 (pairs 2ty, 2ty+1)
    const int p   = tid & 15;       // A loader: pair 0..15 (rows 2p, 2p+1)
    const int kq  = tid >> 4;       // A loader: k-pair (k = 2kq, 2kq+1)
    const int wk  = tid >> 3;       // W loader: k row 0..15
    const int wc  = tid & 7;        // W loader: col quad base

    ull acc[2][8];
#pragma unroll
    for (int i = 0; i < 2; i++)
#pragma unroll
        for (int j = 0; j < 8; j++) acc[i][j] = 0;

    float2 x0, x1;
    float4 wv0, wv1, wv2, wv3;

#define LOAD_T(kt)                                                             \
    {                                                                          \
        int kg = koff + (kt) * 16 + 2 * kq;                                    \
        const float* ap = A0 + (size_t)(rowBase + 2 * p) * lda + kg;           \
        x0 = *(const float2*)ap;                                               \
        x1 = *(const float2*)(ap + lda);                                       \
        if (NSRC > 1) {                                                        \
            _Pragma("unroll")                                                  \
            for (int s = 1; s < NSRC; s++) {                                   \
                const float* bp = ap + s * srcStride;                          \
                float2 u0 = *(const float2*)bp;                                \
                float2 u1 = *(const float2*)(bp + lda);                        \
                x0.x += u0.x; x0.y += u0.y;                                    \
                x1.x += u1.x; x1.y += u1.y;                                    \
            }                                                                  \
            float2 bb = *(const float2*)(kb + kg);                             \
            x0.x = fmaxf(x0.x + bb.x, 0.f);                                    \
            x0.y = fmaxf(x0.y + bb.y, 0.f);                                    \
            x1.x = fmaxf(x1.x + bb.x, 0.f);                                    \
            x1.y = fmaxf(x1.y + bb.y, 0.f);                                    \
        }                                                                      \
        const float* wp = Wt + (size_t)(koff + (kt) * 16 + wk) * ldw           \
                          + colBase + 4 * wc;                                  \
        wv0 = *(const float4*)wp;                                              \
        wv1 = *(const float4*)(wp + 32);                                       \
        wv2 = *(const float4*)(wp + 64);                                       \
        wv3 = *(const float4*)(wp + 96);                                       \
    }

#define STORE_T(bi)                                                            \
    {                                                                          \
        ull* as = As + (bi) * ABUF;                                            \
        as[(2 * kq + 0) * A_PITCH + p] = pack2(x0.x, x1.x);                    \
        as[(2 * kq + 1) * A_PITCH + p] = pack2(x0.y, x1.y);                    \
        float* ws = Ws + (bi) * WBUF;                                          \
        *(float4*)(ws + wk * W_PITCH + 4 * wc)      = wv0;                     \
        *(float4*)(ws + wk * W_PITCH + 4 * wc + 32) = wv1;                     \
        *(float4*)(ws + wk * W_PITCH + 4 * wc + 64) = wv2;                     \
        *(float4*)(ws + wk * W_PITCH + 4 * wc + 96) = wv3;                     \
    }

    LOAD_T(0);
    STORE_T(0);
    __syncthreads();

#pragma unroll 1
    for (int kt = 0; kt < nkt; kt++) {
        if (kt + 1 < nkt) LOAD_T(kt + 1);
        {
            const ull*   as = As + (kt & 1) * ABUF;
            const float* ws = Ws + (kt & 1) * WBUF;
#pragma unroll
            for (int kk = 0; kk < 16; kk++) {
                ulonglong2 aA = *(const ulonglong2*)&as[kk * A_PITCH + 2 * ty];
                float4 wa = *(const float4*)&ws[kk * W_PITCH + 4 * tx];
                float4 wb = *(const float4*)&ws[kk * W_PITCH + 64 + 4 * tx];
                ull w0 = pack2(wa.x, wa.x), w1 = pack2(wa.y, wa.y);
                ull w2 = pack2(wa.z, wa.z), w3 = pack2(wa.w, wa.w);
                ull w4 = pack2(wb.x, wb.x), w5 = pack2(wb.y, wb.y);
                ull w6 = pack2(wb.z, wb.z), w7 = pack2(wb.w, wb.w);
                fma2(acc[0][0], aA.x, w0); fma2(acc[0][1], aA.x, w1);
                fma2(acc[0][2], aA.x, w2); fma2(acc[0][3], aA.x, w3);
                fma2(acc[0][4], aA.x, w4); fma2(acc[0][5], aA.x, w5);
                fma2(acc[0][6], aA.x, w6); fma2(acc[0][7], aA.x, w7);
                fma2(acc[1][0], aA.y, w0); fma2(acc[1][1], aA.y, w1);
                fma2(acc[1][2], aA.y, w2); fma2(acc[1][3], aA.y, w3);
                fma2(acc[1][4], aA.y, w4); fma2(acc[1][5], aA.y, w5);
                fma2(acc[1][6], aA.y, w6); fma2(acc[1][7], aA.y, w7);
            }
        }
        if (kt + 1 < nkt) STORE_T((kt + 1) & 1);
        __syncthreads();
    }
#undef LOAD_T
#undef STORE_T

    float4 b0, b1;
    if (EPI == EPI_TANH) {
        b0 = *(const float4*)(bias + colBase + 4 * tx);
        b1 = *(const float4*)(bias + colBase + 64 + 4 * tx);
    }
#pragma unroll
    for (int pp = 0; pp < 2; pp++) {
        float e[8], o[8];
#pragma unroll
        for (int j = 0; j < 8; j++) unpack2(acc[pp][j], e[j], o[j]);
        float4 elo = make_float4(e[0], e[1], e[2], e[3]);
        float4 ehi = make_float4(e[4], e[5], e[6], e[7]);
        float4 olo = make_float4(o[0], o[1], o[2], o[3]);
        float4 ohi = make_float4(o[4], o[5], o[6], o[7]);
        if (EPI == EPI_TANH) {
            elo.x = tanhf(elo.x + b0.x); elo.y = tanhf(elo.y + b0.y);
            elo.z = tanhf(elo.z + b0.z); elo.w = tanhf(elo.w + b0.w);
            ehi.x = tanhf(ehi.x + b1.x); ehi.y = tanhf(ehi.y + b1.y);
            ehi.z = tanhf(ehi.z + b1.z); ehi.w = tanhf(ehi.w + b1.w);
            olo.x = tanhf(olo.x + b0.x); olo.y = tanhf(olo.y + b0.y);
            olo.z = tanhf(olo.z + b0.z); olo.w = tanhf(olo.w + b0.w);
            ohi.x = tanhf(ohi.x + b1.x); ohi.y = tanhf(ohi.y + b1.y);
            ohi.z = tanhf(ohi.z + b1.z); ohi.w = tanhf(ohi.w + b1.w);
        }
        float* c0 = C + (size_t)(rowBase + 4 * ty + 2 * pp) * ldc + colBase + 4 * tx;
        float* c1 = c0 + ldc;
        *(float4*)c0        = elo;
        *(float4*)(c0 + 64) = ehi;
        *(float4*)c1        = olo;
        *(float4*)(c1 + 64) = ohi;
    }
}

// MLP quarter-job j in [0,256): rt(0..7) x ct(0..3) x kh(0..7); 32x128, K=64
__device__ __forceinline__ void mlp_job(int ph, int j, const float* b1,
                                        const float* b2, ull* As, float* Ws)
{
    int rt = j >> 5, ct = (j >> 3) & 3, kh = j & 7;
    int rb = rt * 32, cb = ct * 128, ko = kh * 64;
    if (ph == 0)
        gemm4x8<EPI_RAW, 1>(&g_com[0][0], 0, 0, H2, ko, g_W1t, H2, 0,
                            &g_a1p[kh][0][0], H2, rb, cb, 4, As, Ws);
    else if (ph == 1)
        gemm4x8<EPI_RAW, 8>(&g_a1p[0][0][0], (size_t)BB * H2, b1, H2, ko,
                            g_W2t, H2, 0, &g_a2p[kh][0][0], H2, rb, cb, 4, As, Ws);
    else
        gemm4x8<EPI_RAW, 8>(&g_a2p[0][0][0], (size_t)BB * H2, b2, H2, ko,
                            g_W3t, H2, 0, &g_a3p[kh][0][0], H2, rb, cb, 4, As, Ws);
}

// gate quarter-job g in [0,384): g<192 gi else gh;
// q -> rt(0..7) x ct(0..5) x kh(0..3); 32x128, K=64
__device__ __forceinline__ void gate_job(int g, ull* As, float* Ws)
{
    bool is_gi = g < 192;
    int q = is_gi ? g : g - 192;
    int rt = q / 24, rem = q % 24, ct = rem >> 2, kh = rem & 3;
    int rb = rt * 32, cb = ct * 128, ko = kh * 64;
    if (is_gi)
        gemm4x8<EPI_RAW, 1>(&g_c[0][0], 0, 0, HH, ko, g_WihT, H3, 0,
                            &g_gip[kh][0][0], H3, rb, cb, 4, As, Ws);
    else
        gemm4x8<EPI_RAW, 1>(&g_h[0][0], 0, 0, HH, ko, g_WhhT, H3, 0,
                            &g_ghp[kh][0][0], H3, rb, cb, 4, As, Ws);
}

// =========================== persistent megakernel ===========================
__global__ void __launch_bounds__(NTHR, 1)
rnn_persistent(const float* __restrict__ input, const float* __restrict__ noise,
               const float* __restrict__ Wcin, const float* __restrict__ bcin,
               const float* __restrict__ W1, const float* __restrict__ b1,
               const float* __restrict__ W2, const float* __restrict__ b2,
               const float* __restrict__ W3, const float* __restrict__ b3,
               const float* __restrict__ W4, const float* __restrict__ b4,
               const float* __restrict__ Wih, const float* __restrict__ Whh,
               const float* __restrict__ bih, const float* __restrict__ bhh,
               float* __restrict__ outC, float* __restrict__ outH,
               float* __restrict__ outF)
{
    __shared__ __align__(16) ull   sAs[2 * ABUF];
    __shared__ __align__(16) float sWs[2 * WBUF];
    __shared__ float su[16];

    const int bid = blockIdx.x;
    const int tid = threadIdx.x;
    const int gt  = bid * NTHR + tid;

    unsigned kG = g_epochG;

    // -------- weight transposes (once per launch) --------
    for (int i = gt; i < H2 * H2; i += GSTRIDE) {
        int k = i / H2, n = i % H2;
        g_W1t[i] = W1[(size_t)n * H2 + k];
        g_W2t[i] = W2[(size_t)n * H2 + k];
        g_W3t[i] = W3[(size_t)n * H2 + k];
    }
    for (int i = gt; i < HH * H3; i += GSTRIDE) {
        int k = i / H3, n = i % H3;
        g_WihT[i] = Wih[(size_t)n * HH + k];
        g_WhhT[i] = Whh[(size_t)n * HH + k];
    }
    for (int i = gt; i < II * HH; i += GSTRIDE) {
        int k = i / HH, n = i % HH;
        g_WcinT[i] = Wcin[(size_t)n * II + k];
    }
    barrier_G(++kG);

    // -------- prologue: c_in = tanh(x @ Wcin^T) -> c_concat (row = b*T+t) --------
    for (int j = bid; j < 8192; j += GRID) {
        int rt = j >> 1, ct = j & 1;
        gemm4x8<EPI_TANH, 1>(input, 0, 0, II, 0, g_WcinT, HH, bcin,
                             outC, HH, rt * 32, ct * 128, 8, sAs, sWs);
    }
    barrier_G(++kG);

    // -------- init state --------
    for (int b = bid; b < BB; b += GRID) {
        for (int j = tid; j < HH; j += NTHR) {
            g_c[b][j] = 0.f;
            g_h[b][j] = 0.f;
            g_com[b][j] = 0.f;
            g_com[b][HH + j] = outC[(size_t)b * TT * HH + j];
        }
        if (tid == 0) g_n[b] = 0.f;
    }
    barrier_G(++kG);

    // -------- recurrent loop --------
    for (int t = 0; t < TT; t++) {
        // 3 phases; each phase = 256 MLP quarters + 128 gate quarters = 384
        // jobs over 148 CTAs in 3 static slots (CTAs 0..87 take 3, 88..147 take 2)
#pragma unroll 1
        for (int ph = 0; ph < 3; ph++) {
#pragma unroll 1
            for (int slot = 0; slot < 3; slot++) {
                int j = bid + slot * GRID;
                if (j < 384) {
                    if (j < 256) mlp_job(ph, j, b1, b2, sAs, sWs);
                    else         gate_job(ph * 128 + (j - 256), sAs, sWs);
                }
            }
            barrier_G(++kG);
        }

        // -------- phase U: 2 batch rows per CTA --------
#pragma unroll 1
        for (int rep = 0; rep < 2; rep++) {
            int b = bid + rep * GRID;
            if (b < BB) {
                float part = 0.f;
#pragma unroll
                for (int q = 0; q < 4; q++) {
                    int k = tid + q * NTHR;
                    float v = b3[k];
#pragma unroll
                    for (int s = 0; s < 8; s++) v += g_a3p[s][b][k];
                    part += fmaxf(v, 0.f) * W4[k];
                }
#pragma unroll
                for (int sh = 16; sh > 0; sh >>= 1)
                    part += __shfl_down_sync(0xffffffffu, part, sh);
                if ((tid & 31) == 0) su[tid >> 5] = part;
                __syncthreads();
                if (tid == 0) {
                    float logit = b4[0] + su[0] + su[1] + su[2] + su[3];
                    float u = noise[(size_t)t * BB + b];
                    float logistic = logf(u) - log1pf(-u);
                    float a = sigf((logit + logistic) * 10.f);   // / TEMP
                    float nold = g_n[b];
                    su[8] = a;
                    su[9] = nold;
                    g_n[b] = nold * (1.f - a) + 1.f;
                }
                __syncthreads();
                float alpha = su[8], nold = su[9];
                float nnew = nold * (1.f - alpha) + 1.f;
#pragma unroll
                for (int u2 = 0; u2 < 2; u2++) {
                    int jj = tid + u2 * NTHR;
                    float c = g_c[b][jj], h = g_h[b][jj];
                    float cin = outC[(size_t)b * TT * HH + (size_t)t * HH + jj];
                    float gir = bih[jj],          ghr = bhh[jj];
                    float giz = bih[HH + jj],     ghz = bhh[HH + jj];
                    float gin = bih[2 * HH + jj], ghn = bhh[2 * HH + jj];
#pragma unroll
                    for (int s = 0; s < 4; s++) {
                        gir += g_gip[s][b][jj];
                        ghr += g_ghp[s][b][jj];
                        giz += g_gip[s][b][HH + jj];
                        ghz += g_ghp[s][b][HH + jj];
                        gin += g_gip[s][b][2 * HH + jj];
                        ghn += g_ghp[s][b][2 * HH + jj];
                    }
                    float r  = sigf(gir + ghr);
                    float z  = sigf(giz + ghz);
                    float ng = tanhf(gin + r * ghn);
                    float hcand = (1.f - z) * ng + z * h;
                    float hnew = h * (1.f - alpha) + alpha * hcand;
                    float cnew = (c * nold * (1.f - alpha) + cin) / nnew;
                    g_c[b][jj] = cnew;
                    g_h[b][jj] = hnew;
                    outH[(size_t)b * TT * HH + (size_t)t * HH + jj] = hnew;
                    g_com[b][jj] = cnew;
                    if (t + 1 < TT)
                        g_com[b][HH + jj] = outC[(size_t)b * TT * HH + (size_t)(t + 1) * HH + jj];
                }
                __syncthreads();
            }
        }
        barrier_G(++kG);
    }

    // -------- epilogue: h_final = gru_cell(c_T, h_T) --------
#pragma unroll 1
    for (int slot = 0; slot < 3; slot++) {
        int j = bid + slot * GRID;
        if (j < 384) gate_job(j, sAs, sWs);
    }
    barrier_G(++kG);
    for (int b = bid; b < BB; b += GRID) {
#pragma unroll
        for (int u2 = 0; u2 < 2; u2++) {
            int jj = tid + u2 * NTHR;
            float h = g_h[b][jj];
            float gir = bih[jj],          ghr = bhh[jj];
            float giz = bih[HH + jj],     ghz = bhh[HH + jj];
            float gin = bih[2 * HH + jj], ghn = bhh[2 * HH + jj];
#pragma unroll
            for (int s = 0; s < 4; s++) {
                gir += g_gip[s][b][jj];
                ghr += g_ghp[s][b][jj];
                giz += g_gip[s][b][HH + jj];
                ghz += g_ghp[s][b][HH + jj];
                gin += g_gip[s][b][2 * HH + jj];
                ghn += g_ghp[s][b][2 * HH + jj];
            }
            float r  = sigf(gir + ghr);
            float z  = sigf(giz + ghz);
            float ng = tanhf(gin + r * ghn);
            outF[(size_t)b * HH + jj] = (1.f - z) * ng + z * h;
        }
    }

    // persist episode base for the next launch / graph replay
    if (bid == 0 && tid == 0) g_epochG = kG;
}

extern "C" void kernel_launch(void* const* d_in, const int* in_sizes, int n_in,
                              void* d_out, int out_size)
{
    const float* input = (const float*)d_in[0];
    const float* noise = (const float*)d_in[1];
    const float* Wcin  = (const float*)d_in[2];
    const float* bcin  = (const float*)d_in[3];
    const float* W1    = (const float*)d_in[4];
    const float* b1    = (const float*)d_in[5];
    const float* W2    = (const float*)d_in[6];
    const float* b2    = (const float*)d_in[7];
    const float* W3    = (const float*)d_in[8];
    const float* b3    = (const float*)d_in[9];
    const float* W4    = (const float*)d_in[10];
    const float* b4    = (const float*)d_in[11];
    const float* Wih   = (const float*)d_in[12];
    const float* Whh   = (const float*)d_in[13];
    const float* bih   = (const float*)d_in[14];
    const float* bhh   = (const float*)d_in[15];

    float* outC = (float*)d_out;                   // c_concat [B,T,H]
    float* outH = outC + (size_t)BB * TT * HH;     // h_concat [B,T,H]
    float* outF = outH + (size_t)BB * TT * HH;     // h_final  [B,H]

    rnn_persistent<<<GRID, NTHR>>>(input, noise, Wcin, bcin, W1, b1, W2, b2,
                                   W3, b3, W4, b4, Wih, Whh, bih, bhh,
                                   outC, outH, outF);
}

// round 17
// speedup vs baseline: 1.4547x; 1.4547x over previous
#include <cuda_runtime.h>
#include <math.h>

#define BB 256
#define TT 512
#define II 128
#define HH 256
#define H2 512
#define H3 768
#define SMS 148
#define GRID 148
#define NTHR 128
#define GSTRIDE (GRID * NTHR)

typedef unsigned long long ull;

// gemm8x8 smem geometry: BK=16  (R13 champion geometry, verbatim)
#define A_PITCH 34                 // ull per k-row (32 pairs + 2 pad)
#define W_PITCH 132                // f32 per k-row (128 cols + 4 pad)
#define ABUF (16 * A_PITCH)
#define WBUF (16 * W_PITCH)

enum { EPI_RAW = 0, EPI_TANH = 2 };

// ---------------- persistent device scratch (no allocations) ----------------
__device__ float g_W1t[H2 * H2];     // transposed: Wt[k][n] = W[n][k]
__device__ float g_W2t[H2 * H2];
__device__ float g_W3t[H2 * H2];
__device__ float g_WihT[HH * H3];
__device__ float g_WhhT[HH * H3];
__device__ float g_WcinT[II * HH];

__device__ float g_com[BB][H2];      // [c | c_in_t]
__device__ float g_a1p[4][BB][H2];   // MLP K-split-4 partials
__device__ float g_a2p[4][BB][H2];
__device__ float g_a3p[4][BB][H2];
__device__ float g_gip[2][BB][H3];   // gate K-split-2 partials (no bias)
__device__ float g_ghp[2][BB][H3];
__device__ float g_c[BB][HH];
__device__ float g_h[BB][HH];
__device__ float g_n[BB];

// ---------------- sync objects (all monotonic, replay-safe) ----------------
__device__ unsigned g_cntF[16 * 32];    // full barrier, 148 members
__device__ volatile unsigned g_genF;
__device__ unsigned g_cntM1[8 * 32];    // MLP barrier (64 members) after a1
__device__ volatile unsigned g_genM1;
__device__ unsigned g_cntM2[8 * 32];    // MLP barrier after a2
__device__ volatile unsigned g_genM2;
__device__ unsigned g_cntA3[4 * 32];    // per-rowblock a3 completion (16/step)
__device__ unsigned g_cntGate;          // gate-job completion (96/step)
__device__ unsigned g_epochF, g_epochM1, g_epochM2;

__device__ __forceinline__ void barrier_F(unsigned k)
{
    __syncthreads();
    if (threadIdx.x == 0) {
        __threadfence();
        atomicAdd(&g_cntF[(blockIdx.x & 15) << 5], 1u);
        if (blockIdx.x == 0) {
            unsigned long long need = (unsigned long long)k * GRID;
            for (;;) {
                unsigned long long s = 0;
#pragma unroll
                for (int i = 0; i < 16; i++)
                    s += ((volatile unsigned*)g_cntF)[i << 5];
                if (s >= need) break;
                __nanosleep(32);
            }
            __threadfence();
            g_genF = k;
        } else {
            while (g_genF < k) __nanosleep(48);
        }
        __threadfence();
    }
    __syncthreads();
}

// 64-member barrier among bids 0..63 only
__device__ __forceinline__ void barrier_M(unsigned* cnt, volatile unsigned* gen,
                                          unsigned k)
{
    __syncthreads();
    if (threadIdx.x == 0) {
        __threadfence();
        atomicAdd(&cnt[(blockIdx.x & 7) << 5], 1u);
        if (blockIdx.x == 0) {
            unsigned long long need = (unsigned long long)k * 64u;
            for (;;) {
                unsigned long long s = 0;
#pragma unroll
                for (int i = 0; i < 8; i++)
                    s += ((volatile unsigned*)cnt)[i << 5];
                if (s >= need) break;
                __nanosleep(32);
            }
            __threadfence();
            *gen = k;
        } else {
            while (*gen < k) __nanosleep(32);
        }
        __threadfence();
    }
    __syncthreads();
}

__device__ __forceinline__ float sigf(float x) { return 1.f / (1.f + expf(-x)); }

__device__ __forceinline__ ull pack2(float x, float y) {
    ull r; asm("mov.b64 %0,{%1,%2};" : "=l"(r) : "f"(x), "f"(y)); return r;
}
__device__ __forceinline__ void unpack2(ull v, float& x, float& y) {
    asm("mov.b64 {%0,%1},%2;" : "=f"(x), "=f"(y) : "l"(v));
}
__device__ __forceinline__ void fma2(ull& d, ull a, ull b) {
    asm("fma.rn.f32x2 %0, %1, %2, %0;" : "+l"(d) : "l"(a), "l"(b));
}

// -------------------------------------------------------------------------
// 64x128 output tile, K=128 (8 k-tiles of 16), 128 threads, per-thread 8x8.
// (R13 champion GEMM, verbatim.)
// -------------------------------------------------------------------------
template<int EPI, int NSRC>
__device__ __noinline__ void gemm8x8(
    const float* __restrict__ A0, size_t srcStride, const float* __restrict__ kb,
    int lda, int koff,
    const float* __restrict__ Wt, int ldw,
    const float* __restrict__ bias,
    float* __restrict__ C, int ldc,
    int rowBase, int colBase,
    ull* __restrict__ As, float* __restrict__ Ws)
{
    const int tid = threadIdx.x;
    const int tx  = tid & 15;
    const int ty  = tid >> 4;
    const int p   = tid >> 2;
    const int kq  = tid & 3;
    const int wk  = tid >> 3;
    const int wc  = tid & 7;

    ull acc[4][8];
#pragma unroll
    for (int i = 0; i < 4; i++)
#pragma unroll
        for (int j = 0; j < 8; j++) acc[i][j] = 0;

    float4 x0, x1, wv0, wv1, wv2, wv3;

#define LOAD_T(kt)                                                             \
    {                                                                          \
        int kg = koff + (kt) * 16 + 4 * kq;                                    \
        const float* ap = A0 + (size_t)(rowBase + 2 * p) * lda + kg;           \
        x0 = *(const float4*)ap;                                               \
        x1 = *(const float4*)(ap + lda);                                       \
        if (NSRC == 4) {                                                       \
            _Pragma("unroll")                                                  \
            for (int s = 1; s < 4; s++) {                                      \
                const float* bp = ap + s * srcStride;                          \
                float4 u0 = *(const float4*)bp;                                \
                float4 u1 = *(const float4*)(bp + lda);                        \
                x0.x += u0.x; x0.y += u0.y; x0.z += u0.z; x0.w += u0.w;        \
                x1.x += u1.x; x1.y += u1.y; x1.z += u1.z; x1.w += u1.w;        \
            }                                                                  \
            float4 bb = *(const float4*)(kb + kg);                             \
            x0.x = fmaxf(x0.x + bb.x, 0.f);                                    \
            x0.y = fmaxf(x0.y + bb.y, 0.f);                                    \
            x0.z = fmaxf(x0.z + bb.z, 0.f);                                    \
            x0.w = fmaxf(x0.w + bb.w, 0.f);                                    \
            x1.x = fmaxf(x1.x + bb.x, 0.f);                                    \
            x1.y = fmaxf(x1.y + bb.y, 0.f);                                    \
            x1.z = fmaxf(x1.z + bb.z, 0.f);                                    \
            x1.w = fmaxf(x1.w + bb.w, 0.f);                                    \
        }                                                                      \
        const float* wp = Wt + (size_t)(koff + (kt) * 16 + wk) * ldw           \
                          + colBase + 4 * wc;                                  \
        wv0 = *(const float4*)wp;                                              \
        wv1 = *(const float4*)(wp + 32);                                       \
        wv2 = *(const float4*)(wp + 64);                                       \
        wv3 = *(const float4*)(wp + 96);                                       \
    }

#define STORE_T(bi)                                                            \
    {                                                                          \
        ull* as = As + (bi) * ABUF;                                            \
        as[(4 * kq + 0) * A_PITCH + p] = pack2(x0.x, x1.x);                    \
        as[(4 * kq + 1) * A_PITCH + p] = pack2(x0.y, x1.y);                    \
        as[(4 * kq + 2) * A_PITCH + p] = pack2(x0.z, x1.z);                    \
        as[(4 * kq + 3) * A_PITCH + p] = pack2(x0.w, x1.w);                    \
        float* ws = Ws + (bi) * WBUF;                                          \
        *(float4*)(ws + wk * W_PITCH + 4 * wc)      = wv0;                     \
        *(float4*)(ws + wk * W_PITCH + 4 * wc + 32) = wv1;                     \
        *(float4*)(ws + wk * W_PITCH + 4 * wc + 64) = wv2;                     \
        *(float4*)(ws + wk * W_PITCH + 4 * wc + 96) = wv3;                     \
    }

    LOAD_T(0);
    STORE_T(0);
    __syncthreads();

#pragma unroll 1
    for (int kt = 0; kt < 8; kt++) {
        if (kt < 7) LOAD_T(kt + 1);
        {
            const ull*   as = As + (kt & 1) * ABUF;
            const float* ws = Ws + (kt & 1) * WBUF;
#pragma unroll
            for (int kk = 0; kk < 16; kk++) {
                ulonglong2 aA = *(const ulonglong2*)&as[kk * A_PITCH + 4 * ty];
                ulonglong2 aB = *(const ulonglong2*)&as[kk * A_PITCH + 4 * ty + 2];
                float4 wa = *(const float4*)&ws[kk * W_PITCH + 4 * tx];
                float4 wb = *(const float4*)&ws[kk * W_PITCH + 64 + 4 * tx];
                ull w0 = pack2(wa.x, wa.x), w1 = pack2(wa.y, wa.y);
                ull w2 = pack2(wa.z, wa.z), w3 = pack2(wa.w, wa.w);
                ull w4 = pack2(wb.x, wb.x), w5 = pack2(wb.y, wb.y);
                ull w6 = pack2(wb.z, wb.z), w7 = pack2(wb.w, wb.w);
                fma2(acc[0][0], aA.x, w0); fma2(acc[0][1], aA.x, w1);
                fma2(acc[0][2], aA.x, w2); fma2(acc[0][3], aA.x, w3);
                fma2(acc[0][4], aA.x, w4); fma2(acc[0][5], aA.x, w5);
                fma2(acc[0][6], aA.x, w6); fma2(acc[0][7], aA.x, w7);
                fma2(acc[1][0], aA.y, w0); fma2(acc[1][1], aA.y, w1);
                fma2(acc[1][2], aA.y, w2); fma2(acc[1][3], aA.y, w3);
                fma2(acc[1][4], aA.y, w4); fma2(acc[1][5], aA.y, w5);
                fma2(acc[1][6], aA.y, w6); fma2(acc[1][7], aA.y, w7);
                fma2(acc[2][0], aB.x, w0); fma2(acc[2][1], aB.x, w1);
                fma2(acc[2][2], aB.x, w2); fma2(acc[2][3], aB.x, w3);
                fma2(acc[2][4], aB.x, w4); fma2(acc[2][5], aB.x, w5);
                fma2(acc[2][6], aB.x, w6); fma2(acc[2][7], aB.x, w7);
                fma2(acc[3][0], aB.y, w0); fma2(acc[3][1], aB.y, w1);
                fma2(acc[3][2], aB.y, w2); fma2(acc[3][3], aB.y, w3);
                fma2(acc[3][4], aB.y, w4); fma2(acc[3][5], aB.y, w5);
                fma2(acc[3][6], aB.y, w6); fma2(acc[3][7], aB.y, w7);
            }
        }
        if (kt < 7) STORE_T((kt + 1) & 1);
        __syncthreads();
    }
#undef LOAD_T
#undef STORE_T

    float4 b0, b1;
    if (EPI == EPI_TANH) {
        b0 = *(const float4*)(bias + colBase + 4 * tx);
        b1 = *(const float4*)(bias + colBase + 64 + 4 * tx);
    }
#pragma unroll
    for (int pp = 0; pp < 4; pp++) {
        float e[8], o[8];
#pragma unroll
        for (int j = 0; j < 8; j++) unpack2(acc[pp][j], e[j], o[j]);
        float4 elo = make_float4(e[0], e[1], e[2], e[3]);
        float4 ehi = make_float4(e[4], e[5], e[6], e[7]);
        float4 olo = make_float4(o[0], o[1], o[2], o[3]);
        float4 ohi = make_float4(o[4], o[5], o[6], o[7]);
        if (EPI == EPI_TANH) {
            elo.x = tanhf(elo.x + b0.x); elo.y = tanhf(elo.y + b0.y);
            elo.z = tanhf(elo.z + b0.z); elo.w = tanhf(elo.w + b0.w);
            ehi.x = tanhf(ehi.x + b1.x); ehi.y = tanhf(ehi.y + b1.y);
            ehi.z = tanhf(ehi.z + b1.z); ehi.w = tanhf(ehi.w + b1.w);
            olo.x = tanhf(olo.x + b0.x); olo.y = tanhf(olo.y + b0.y);
            olo.z = tanhf(olo.z + b0.z); olo.w = tanhf(olo.w + b0.w);
            ohi.x = tanhf(ohi.x + b1.x); ohi.y = tanhf(ohi.y + b1.y);
            ohi.z = tanhf(ohi.z + b1.z); ohi.w = tanhf(ohi.w + b1.w);
        }
        float* c0 = C + (size_t)(rowBase + 8 * ty + 2 * pp) * ldc + colBase + 4 * tx;
        float* c1 = c0 + ldc;
        *(float4*)c0        = elo;
        *(float4*)(c0 + 64) = ehi;
        *(float4*)c1        = olo;
        *(float4*)(c1 + 64) = ohi;
    }
}

// MLP job j in [0,64): rt(0..3) x ct(0..3) x kh(0..3); 64x128 tile, K=128
__device__ __forceinline__ void mlp_job(int ph, int j, const float* b1,
                                        const float* b2, ull* As, float* Ws)
{
    int rt = j >> 4, ct = (j >> 2) & 3, kh = j & 3;
    int rb = rt * 64, cb = ct * 128, ko = kh * 128;
    if (ph == 0)
        gemm8x8<EPI_RAW, 1>(&g_com[0][0], 0, 0, H2, ko, g_W1t, H2, 0,
                            &g_a1p[kh][0][0], H2, rb, cb, As, Ws);
    else if (ph == 1)
        gemm8x8<EPI_RAW, 4>(&g_a1p[0][0][0], (size_t)BB * H2, b1, H2, ko,
                            g_W2t, H2, 0, &g_a2p[kh][0][0], H2, rb, cb, As, Ws);
    else
        gemm8x8<EPI_RAW, 4>(&g_a2p[0][0][0], (size_t)BB * H2, b2, H2, ko,
                            g_W3t, H2, 0, &g_a3p[kh][0][0], H2, rb, cb, As, Ws);
}

// gate job g in [0,96): g<48 gi else gh; q -> rt(0..3) x ct(0..5) x kh(0..1)
__device__ __forceinline__ void gate_job(int g, ull* As, float* Ws)
{
    bool is_gi = g < 48;
    int q = is_gi ? g : g - 48;
    int rt = q / 12, rem = q % 12, ct = rem >> 1, kh = rem & 1;
    int rb = rt * 64, cb = ct * 128, ko = kh * 128;
    if (is_gi)
        gemm8x8<EPI_RAW, 1>(&g_c[0][0], 0, 0, HH, ko, g_WihT, H3, 0,
                            &g_gip[kh][0][0], H3, rb, cb, As, Ws);
    else
        gemm8x8<EPI_RAW, 1>(&g_h[0][0], 0, 0, HH, ko, g_WhhT, H3, 0,
                            &g_ghp[kh][0][0], H3, rb, cb, As, Ws);
}

// =========================== persistent megakernel ===========================
__global__ void __launch_bounds__(NTHR, 1)
rnn_persistent(const float* __restrict__ input, const float* __restrict__ noise,
               const float* __restrict__ Wcin, const float* __restrict__ bcin,
               const float* __restrict__ W1, const float* __restrict__ b1,
               const float* __restrict__ W2, const float* __restrict__ b2,
               const float* __restrict__ W3, const float* __restrict__ b3,
               const float* __restrict__ W4, const float* __restrict__ b4,
               const float* __restrict__ Wih, const float* __restrict__ Whh,
               const float* __restrict__ bih, const float* __restrict__ bhh,
               float* __restrict__ outC, float* __restrict__ outH,
               float* __restrict__ outF)
{
    __shared__ __align__(16) ull   sAs[2 * ABUF];
    __shared__ __align__(16) float sWs[2 * WBUF];
    __shared__ float su[16];

    const int bid = blockIdx.x;
    const int tid = threadIdx.x;
    const int gt  = bid * NTHR + tid;

    unsigned kF  = g_epochF;
    unsigned kM1 = g_epochM1;
    unsigned kM2 = g_epochM2;
    // counter bases (previous launches' totals; stable before any work starts)
    const unsigned a3base   = g_cntA3[0];
    const unsigned gateBase = g_cntGate;

    // -------- weight transposes (once per launch) --------
    for (int i = gt; i < H2 * H2; i += GSTRIDE) {
        int k = i / H2, n = i % H2;
        g_W1t[i] = W1[(size_t)n * H2 + k];
        g_W2t[i] = W2[(size_t)n * H2 + k];
        g_W3t[i] = W3[(size_t)n * H2 + k];
    }
    for (int i = gt; i < HH * H3; i += GSTRIDE) {
        int k = i / H3, n = i % H3;
        g_WihT[i] = Wih[(size_t)n * HH + k];
        g_WhhT[i] = Whh[(size_t)n * HH + k];
    }
    for (int i = gt; i < II * HH; i += GSTRIDE) {
        int k = i / HH, n = i % HH;
        g_WcinT[i] = Wcin[(size_t)n * II + k];
    }
    barrier_F(++kF);

    // -------- prologue: c_in = tanh(x @ Wcin^T) -> c_concat (row = b*T+t) --------
    for (int j = bid; j < 4096; j += GRID) {
        int rt = j >> 1, ct = j & 1;
        gemm8x8<EPI_TANH, 1>(input, 0, 0, II, 0, g_WcinT, HH, bcin,
                             outC, HH, rt * 64, ct * 128, sAs, sWs);
    }
    barrier_F(++kF);

    // -------- init state --------
    for (int b = bid; b < BB; b += GRID) {
        for (int j = tid; j < HH; j += NTHR) {
            g_c[b][j] = 0.f;
            g_h[b][j] = 0.f;
            g_com[b][j] = 0.f;
            g_com[b][HH + j] = outC[(size_t)b * TT * HH + j];
        }
        if (tid == 0) g_n[b] = 0.f;
    }
    barrier_F(++kF);

    // -------- recurrent loop --------
    for (int t = 0; t < TT; t++) {
        if (bid < 64) {
            // MLP chain: a1 -> a2 -> a3 with 64-member barriers
            mlp_job(0, bid, b1, b2, sAs, sWs);
            barrier_M(g_cntM1, &g_genM1, ++kM1);
            mlp_job(1, bid, b1, b2, sAs, sWs);
            barrier_M(g_cntM2, &g_genM2, ++kM2);
            mlp_job(2, bid, b1, b2, sAs, sWs);
            __syncthreads();
            if (tid == 0) {
                __threadfence();
                atomicAdd(&g_cntA3[(bid >> 4) << 5], 1u);  // rowblock = bid>>4
            }
        } else {
            kM1++; kM2++;                       // keep episode counts coherent
            int g = bid - 64;                   // gate jobs 0..83
            gate_job(g, sAs, sWs);
            __syncthreads();
            if (tid == 0) { __threadfence(); atomicAdd(&g_cntGate, 1u); }
            if (g < 12) {                       // gate jobs 84..95
                gate_job(84 + g, sAs, sWs);
                __syncthreads();
                if (tid == 0) { __threadfence(); atomicAdd(&g_cntGate, 1u); }
            }
        }

        // -------- phase U: spin on a3 rowblock + gate counters, 2 rows/CTA ----
#pragma unroll 1
        for (int rep = 0; rep < 2; rep++) {
            int b = bid + rep * GRID;
            if (b < BB) {
                if (tid == 0) {
                    unsigned tgtA = a3base + 16u * (unsigned)(t + 1);
                    unsigned tgtG = gateBase + 96u * (unsigned)(t + 1);
                    while (((volatile unsigned*)g_cntA3)[(b >> 6) << 5] < tgtA)
                        __nanosleep(48);
                    while (*(volatile unsigned*)&g_cntGate < tgtG)
                        __nanosleep(48);
                    __threadfence();
                }
                __syncthreads();

                float part = 0.f;
#pragma unroll
                for (int q = 0; q < 4; q++) {
                    int k = tid + q * NTHR;
                    float v = g_a3p[0][b][k] + g_a3p[1][b][k] + g_a3p[2][b][k]
                            + g_a3p[3][b][k] + b3[k];
                    part += fmaxf(v, 0.f) * W4[k];
                }
#pragma unroll
                for (int sh = 16; sh > 0; sh >>= 1)
                    part += __shfl_down_sync(0xffffffffu, part, sh);
                if ((tid & 31) == 0) su[tid >> 5] = part;
                __syncthreads();
                if (tid == 0) {
                    float logit = b4[0] + su[0] + su[1] + su[2] + su[3];
                    float u = noise[(size_t)t * BB + b];
                    float logistic = logf(u) - log1pf(-u);
                    float a = sigf((logit + logistic) * 10.f);   // / TEMP
                    float nold = g_n[b];
                    su[8] = a;
                    su[9] = nold;
                    g_n[b] = nold * (1.f - a) + 1.f;
                }
                __syncthreads();
                float alpha = su[8], nold = su[9];
                float nnew = nold * (1.f - alpha) + 1.f;
#pragma unroll
                for (int u2 = 0; u2 < 2; u2++) {
                    int jj = tid + u2 * NTHR;
                    float c = g_c[b][jj], h = g_h[b][jj];
                    float cin = outC[(size_t)b * TT * HH + (size_t)t * HH + jj];
                    float gir = g_gip[0][b][jj] + g_gip[1][b][jj] + bih[jj];
                    float ghr = g_ghp[0][b][jj] + g_ghp[1][b][jj] + bhh[jj];
                    float giz = g_gip[0][b][HH + jj] + g_gip[1][b][HH + jj] + bih[HH + jj];
                    float ghz = g_ghp[0][b][HH + jj] + g_ghp[1][b][HH + jj] + bhh[HH + jj];
                    float gin = g_gip[0][b][2 * HH + jj] + g_gip[1][b][2 * HH + jj] + bih[2 * HH + jj];
                    float ghn = g_ghp[0][b][2 * HH + jj] + g_ghp[1][b][2 * HH + jj] + bhh[2 * HH + jj];
                    float r  = sigf(gir + ghr);
                    float z  = sigf(giz + ghz);
                    float ng = tanhf(gin + r * ghn);
                    float hcand = (1.f - z) * ng + z * h;
                    float hnew = h * (1.f - alpha) + alpha * hcand;
                    float cnew = (c * nold * (1.f - alpha) + cin) / nnew;
                    g_c[b][jj] = cnew;
                    g_h[b][jj] = hnew;
                    outH[(size_t)b * TT * HH + (size_t)t * HH + jj] = hnew;
                    g_com[b][jj] = cnew;
                    if (t + 1 < TT)
                        g_com[b][HH + jj] = outC[(size_t)b * TT * HH + (size_t)(t + 1) * HH + jj];
                }
                __syncthreads();
            }
        }
        barrier_F(++kF);                        // U(t) done -> step t+1 may start
    }

    // -------- epilogue: h_final = gru_cell(c_T, h_T) --------
    if (bid < 96) gate_job(bid, sAs, sWs);      // no counter needed here
    barrier_F(++kF);
    for (int b = bid; b < BB; b += GRID) {
#pragma unroll
        for (int u2 = 0; u2 < 2; u2++) {
            int jj = tid + u2 * NTHR;
            float h = g_h[b][jj];
            float gir = g_gip[0][b][jj] + g_gip[1][b][jj] + bih[jj];
            float ghr = g_ghp[0][b][jj] + g_ghp[1][b][jj] + bhh[jj];
            float giz = g_gip[0][b][HH + jj] + g_gip[1][b][HH + jj] + bih[HH + jj];
            float ghz = g_ghp[0][b][HH + jj] + g_ghp[1][b][HH + jj] + bhh[HH + jj];
            float gin = g_gip[0][b][2 * HH + jj] + g_gip[1][b][2 * HH + jj] + bih[2 * HH + jj];
            float ghn = g_ghp[0][b][2 * HH + jj] + g_ghp[1][b][2 * HH + jj] + bhh[2 * HH + jj];
            float r  = sigf(gir + ghr);
            float z  = sigf(giz + ghz);
            float ng = tanhf(gin + r * ghn);
            outF[(size_t)b * HH + jj] = (1.f - z) * ng + z * h;
        }
    }

    // persist episode bases for next launch / graph replay
    if (bid == 0 && tid == 0) {
        g_epochF = kF;
        g_epochM1 = kM1;
        g_epochM2 = kM2;
    }
}

extern "C" void kernel_launch(void* const* d_in, const int* in_sizes, int n_in,
                              void* d_out, int out_size)
{
    const float* input = (const float*)d_in[0];
    const float* noise = (const float*)d_in[1];
    const float* Wcin  = (const float*)d_in[2];
    const float* bcin  = (const float*)d_in[3];
    const float* W1    = (const float*)d_in[4];
    const float* b1    = (const float*)d_in[5];
    const float* W2    = (const float*)d_in[6];
    const float* b2    = (const float*)d_in[7];
    const float* W3    = (const float*)d_in[8];
    const float* b3    = (const float*)d_in[9];
    const float* W4    = (const float*)d_in[10];
    const float* b4    = (const float*)d_in[11];
    const float* Wih   = (const float*)d_in[12];
    const float* Whh   = (const float*)d_in[13];
    const float* bih   = (const float*)d_in[14];
    const float* bhh   = (const float*)d_in[15];

    float* outC = (float*)d_out;                   // c_concat [B,T,H]
    float* outH = outC + (size_t)BB * TT * HH;     // h_concat [B,T,H]
    float* outF = outH + (size_t)BB * TT * HH;     // h_final  [B,H]

    rnn_persistent<<<GRID, NTHR>>>(input, noise, Wcin, bcin, W1, b1, W2, b2,
                                   W3, b3, W4, b4, Wih, Whh, bih, bhh,
                                   outC, outH, outF);
}